// round 16
// baseline (speedup 1.0000x reference)
#include <cuda_runtime.h>
#include <math.h>

#define NB 8
#define NA 128
#define ND 127
#define NL 9
#define NF 64
#define NK 16
#define LF (NL*NF)       // 576
#define ES 32            // per-edge stride in d_YR/d_gYR: [0..8]=Y, [16..31]=R
#define WS 65            // padded weight row stride
#define XS 65            // padded x/gm row stride
#define SQ3f 1.7320508075688772f
#define CUT2 25.0f
#define CH 8             // edge chunk

// ---------------- scratch ----------------
__device__ float d_YR [(size_t)NB*NA*ND*ES];
__device__ float d_gYR[(size_t)NB*NA*ND*ES];
__device__ float d_aw[3][(size_t)NB*NA*ND*NF];
__device__ float d_rw[3][(size_t)NB*NA*ND*NF];
__device__ float d_dd[(size_t)NB*NA*ND*3];
__device__ int   d_cnt [NB*NA];
__device__ int   d_rcnt[NB*NA];
__device__ int   d_nbr [NB*NA*NA];
__device__ int   d_slot[NB*NA*NA];
__device__ int   d_rnbr[NB*NA*NA];
__device__ int   d_redg[NB*NA*NA];
__device__ float d_x0[(size_t)NB*NA*LF];
__device__ float d_x1[(size_t)NB*NA*LF];
__device__ float d_x2[(size_t)NB*NA*LF];
__device__ float d_y2a[(size_t)NB*NA*LF];
__device__ float d_y2b[(size_t)NB*NA*LF];
__device__ float d_dh0[NB*NA*NF];
__device__ float d_gxA[(size_t)NB*NA*LF];
__device__ float d_gxB[(size_t)NB*NA*LF];
__device__ float d_gy1[(size_t)NB*NA*LF];
__device__ float d_ae[NB*NA];

__constant__ int   c_deg[9]    = {0,1,1,1,2,2,2,2,2};
__constant__ float c_binom[16] = {1.f,15.f,105.f,455.f,1365.f,3003.f,5005.f,6435.f,
                                  6435.f,5005.f,3003.f,1365.f,455.f,105.f,15.f,1.f};

// ---------------- geometry + compaction + separable basis ----------------
__global__ void k_geom(const float* __restrict__ pos){
    int bn = blockIdx.x; int b=bn/NA, dst=bn%NA;
    int j = threadIdx.x;
    float pdx=pos[(b*NA+dst)*3+0], pdy=pos[(b*NA+dst)*3+1], pdz=pos[(b*NA+dst)*3+2];
    float dx=0.f,dy=0.f,dz=0.f,r2=1.f; bool act=false;
    if(j!=dst){
        dx=pos[(b*NA+j)*3+0]-pdx;
        dy=pos[(b*NA+j)*3+1]-pdy;
        dz=pos[(b*NA+j)*3+2]-pdz;
        r2=dx*dx+dy*dy+dz*dz+1e-12f;
        act = (1.f - r2/CUT2) > 1e-6f;
    }
    unsigned m=__ballot_sync(0xffffffffu, act);
    int wid=j>>5, lane=j&31;
    __shared__ int wcnt[4];
    if(lane==0) wcnt[wid]=__popc(m);
    __syncthreads();
    int basec=0;
    #pragma unroll
    for(int w=0;w<4;w++) if(w<wid) basec+=wcnt[w];
    int slot = basec + __popc(m & ((1u<<lane)-1u));
    if(j==0) d_cnt[bn]=wcnt[0]+wcnt[1]+wcnt[2]+wcnt[3];
    d_slot[bn*NA+j] = act ? slot : -1;
    if(!act) return;
    d_nbr[bn*NA+slot]=j;
    float om = 1.f - r2/CUT2;
    float r=sqrtf(r2), inv=1.f/r;
    float ux=dx*inv, uy=dy*inv, uz=dz*inv;
    float Y[9];
    Y[0]=1.f; Y[1]=ux; Y[2]=uy; Y[3]=uz;
    Y[4]=SQ3f*ux*uy; Y[5]=SQ3f*uy*uz; Y[6]=0.5f*(3.f*uz*uz-1.f);
    Y[7]=SQ3f*ux*uz; Y[8]=0.5f*SQ3f*(ux*ux-uy*uy);
    float w=1.f/(1.f+r), v=1.f-w;
    float cut=expf(1.f-1.f/om);
    float vp[16]; vp[0]=1.f;
    #pragma unroll
    for(int q=1;q<16;q++) vp[q]=vp[q-1]*v;
    float* o = d_YR + ((size_t)bn*ND+slot)*ES;
    #pragma unroll
    for(int l=0;l<9;l++) o[l]=Y[l];
    float wk=1.f;
    #pragma unroll
    for(int k=0;k<16;k++){ o[16+k]=c_binom[k]*wk*vp[15-k]*cut; wk*=w; }
}

__global__ void k_rev(){
    int bn=blockIdx.x; int b=bn/NA, j=bn%NA;
    int i=threadIdx.x;
    int s = (i!=j) ? d_slot[(b*NA+i)*NA + j] : -1;
    bool act = s>=0;
    unsigned m=__ballot_sync(0xffffffffu, act);
    int wid=i>>5, lane=i&31;
    __shared__ int wcnt[4];
    if(lane==0) wcnt[wid]=__popc(m);
    __syncthreads();
    int basec=0;
    #pragma unroll
    for(int w=0;w<4;w++) if(w<wid) basec+=wcnt[w];
    int rslot = basec + __popc(m & ((1u<<lane)-1u));
    if(i==0) d_rcnt[bn]=wcnt[0]+wcnt[1]+wcnt[2]+wcnt[3];
    if(act){
        d_rnbr[bn*NA+rslot]=i;
        d_redg[bn*NA+rslot]=(b*NA+i)*ND + s;
    }
}

// ---------------- precompute aw/rw per edge per layer ----------------
__global__ void __launch_bounds__(512,4) k_awrw(const float* __restrict__ WA, const float* __restrict__ WB){
    int bn=blockIdx.x, lay=blockIdx.y;
    int t=threadIdx.x, c=t>>6, ff=t&63;
    __shared__ float sWA[NK*NF], sWB[NK*NF];
    const float* WAl=WA+lay*NK*NF;
    const float* WBl=WB+lay*NK*NF;
    for(int i=t;i<NK*NF;i+=512){ sWA[i]=WAl[i]; sWB[i]=WBl[i]; }
    __syncthreads();
    int cnt=d_cnt[bn];
    float* awl=d_aw[lay]; float* rwl=d_rw[lay];
    for(int base=0;base<cnt;base+=8){
        int s=base+c;
        if(s<cnt){
            const float* gR=d_YR+((size_t)bn*ND+s)*ES+16;
            float sa=0.f, sb=0.f;
            #pragma unroll
            for(int k=0;k<NK;k++){
                float rk=__ldg(&gR[k]);
                sa=fmaf(rk,sWA[k*NF+ff],sa);
                sb=fmaf(rk,sWB[k*NF+ff],sb);
            }
            size_t eo=((size_t)bn*ND+s)*NF+ff;
            awl[eo]=sa; rwl[eo]=sb;
        }
    }
}

// ---------------- init ----------------
__global__ void k_init(const int* __restrict__ z, const float* __restrict__ embed){
    int bn=blockIdx.x; int b=bn/NA, n=bn%NA;
    int f=threadIdx.x;
    float* x=d_x0+(size_t)bn*LF;
    x[f]=embed[z[b*NA+n]*NF+f];
    #pragma unroll
    for(int l=1;l<9;l++) x[l*NF+f]=0.f;
}

// ---------------- fused layer: message + node update (register-prefetch pipeline) ----------------
__global__ void __launch_bounds__(LF,2) k_layer(const float* __restrict__ W1, const float* __restrict__ b1,
                        const float* __restrict__ W2, int layer){
    int bn=blockIdx.x; int b=bn/NA;
    int t=threadIdx.x, l=t/NF, f=t%NF;
    const float* xin = layer? d_x1 : d_x0;
    float* xout = layer? d_x2 : d_x1;
    float* y2out= layer? d_y2b : d_y2a;
    const float* awl=d_aw[layer]; const float* rwl=d_rw[layer];
    __shared__ float sY[CH][16];
    __shared__ float saw[CH][NF], srw[CH][NF];
    __shared__ float sxs[CH][LF];
    __shared__ float sy[LF];
    int cnt=d_cnt[bn];
    int cg6=t>>6, fg6=t&63, cg4=t>>4, ig4=t&15;
    float xv = xin[(size_t)bn*LF+t];
    float acc = xv;
    float pf_xs[CH]; float pf_aw=0.f, pf_rw=0.f, pf_Y=0.f;
    {
        if(layer){
            #pragma unroll
            for(int c=0;c<CH;c++)
                pf_xs[c] = (c<cnt)? xin[((size_t)b*NA+__ldg(&d_nbr[bn*NA+c]))*LF+t] : 0.f;
        } else {
            if(t<CH*NF)
                pf_xs[0] = (cg6<cnt)? xin[((size_t)b*NA+__ldg(&d_nbr[bn*NA+cg6]))*LF+fg6] : 0.f;
        }
        if(t<CH*NF && cg6<cnt){
            size_t eo=((size_t)bn*ND+cg6)*NF+fg6;
            pf_aw=__ldg(&awl[eo]); pf_rw=__ldg(&rwl[eo]);
        }
        if(t<CH*16 && ig4<9 && cg4<cnt)
            pf_Y=d_YR[((size_t)bn*ND+cg4)*ES+ig4];
    }
    for(int base=0;base<cnt;base+=CH){
        __syncthreads();
        if(layer){
            #pragma unroll
            for(int c=0;c<CH;c++) sxs[c][t]=pf_xs[c];
        } else {
            if(t<CH*NF) sxs[cg6][fg6]=pf_xs[0];
        }
        if(t<CH*NF){ saw[cg6][fg6]=pf_aw; srw[cg6][fg6]=pf_rw; }
        if(t<CH*16 && ig4<9) sY[cg4][ig4]=pf_Y;
        __syncthreads();
        int B=base+CH;
        if(B<cnt){
            if(layer){
                #pragma unroll
                for(int c=0;c<CH;c++)
                    pf_xs[c] = (B+c<cnt)? xin[((size_t)b*NA+__ldg(&d_nbr[bn*NA+B+c]))*LF+t] : 0.f;
            } else {
                if(t<CH*NF)
                    pf_xs[0] = (B+cg6<cnt)? xin[((size_t)b*NA+__ldg(&d_nbr[bn*NA+B+cg6]))*LF+fg6] : 0.f;
            }
            if(t<CH*NF && B+cg6<cnt){
                size_t eo=((size_t)bn*ND+B+cg6)*NF+fg6;
                pf_aw=__ldg(&awl[eo]); pf_rw=__ldg(&rwl[eo]);
            }
            if(t<CH*16 && ig4<9 && B+cg4<cnt)
                pf_Y=d_YR[((size_t)bn*ND+B+cg4)*ES+ig4];
        }
        #pragma unroll
        for(int c=0;c<CH;c++) if(base+c<cnt){
            float xs0=sxs[c][f];
            acc = fmaf(sY[c][l]*saw[c][f], xs0, acc);
            if(layer) acc = fmaf(sxs[c][t], srw[c][f], acc);
            else if(l==0) acc = fmaf(xs0, srw[c][f], acc);
        }
    }
    // node phase
    __syncthreads();
    sy[t]=acc;
    __syncthreads();
    int deg=c_deg[l];
    const float* w1=W1+deg*4096;
    float v=0.f;
    for(int h=0;h<NF;h++) v=fmaf(sy[l*NF+h],w1[h*NF+f],v);
    if(l==0) v+=b1[f];
    y2out[(size_t)bn*LF+t]=v;
    __syncthreads();
    sy[t]=v;
    __syncthreads();
    float s=sy[f];
    float sig=1.f/(1.f+expf(-s));
    float y3=(l==0)? s*sig : v*sig;
    __syncthreads();
    sy[t]=y3;
    __syncthreads();
    const float* w2=W2+deg*4096;
    float o=0.f;
    for(int h=0;h<NF;h++) o=fmaf(sy[l*NF+h],w2[h*NF+f],o);
    xout[(size_t)bn*LF+t]=xv+o;
}

// ---------------- fused final: edge messages + scalar MLP fwd/bwd (pipelined) ----------------
__global__ void __launch_bounds__(LF,2) k_final(const int* __restrict__ z,
                        const float* __restrict__ W1s, const float* __restrict__ b1s,
                        const float* __restrict__ W2s, const float* __restrict__ w_out,
                        const float* __restrict__ ebias){
    int bn=blockIdx.x; int b=bn/NA, n=bn%NA;
    int t=threadIdx.x, l=t/NF, f=t%NF;
    const float* awl=d_aw[2]; const float* rwl=d_rw[2];
    __shared__ float sY[CH][16];
    __shared__ float saw[CH][NF], srw[CH][NF];
    __shared__ float sxs[CH][LF];
    __shared__ float sred[LF];
    __shared__ float sh0[NF], sq[NF], sdp[NF], sdh[NF];
    int cnt=d_cnt[bn];
    int cg6=t>>6, fg6=t&63, cg4=t>>4, ig4=t&15;
    float acc=0.f;
    float pf_xs[CH]; float pf_aw=0.f, pf_rw=0.f, pf_Y=0.f;
    {
        #pragma unroll
        for(int c=0;c<CH;c++)
            pf_xs[c] = (c<cnt)? d_x2[((size_t)b*NA+__ldg(&d_nbr[bn*NA+c]))*LF+t] : 0.f;
        if(t<CH*NF && cg6<cnt){
            size_t eo=((size_t)bn*ND+cg6)*NF+fg6;
            pf_aw=__ldg(&awl[eo]); pf_rw=__ldg(&rwl[eo]);
        }
        if(t<CH*16 && ig4<9 && cg4<cnt)
            pf_Y=d_YR[((size_t)bn*ND+cg4)*ES+ig4];
    }
    for(int base=0;base<cnt;base+=CH){
        __syncthreads();
        #pragma unroll
        for(int c=0;c<CH;c++) sxs[c][t]=pf_xs[c];
        if(t<CH*NF){ saw[cg6][fg6]=pf_aw; srw[cg6][fg6]=pf_rw; }
        if(t<CH*16 && ig4<9) sY[cg4][ig4]=pf_Y;
        __syncthreads();
        int B=base+CH;
        if(B<cnt){
            #pragma unroll
            for(int c=0;c<CH;c++)
                pf_xs[c] = (B+c<cnt)? d_x2[((size_t)b*NA+__ldg(&d_nbr[bn*NA+B+c]))*LF+t] : 0.f;
            if(t<CH*NF && B+cg6<cnt){
                size_t eo=((size_t)bn*ND+B+cg6)*NF+fg6;
                pf_aw=__ldg(&awl[eo]); pf_rw=__ldg(&rwl[eo]);
            }
            if(t<CH*16 && ig4<9 && B+cg4<cnt)
                pf_Y=d_YR[((size_t)bn*ND+B+cg4)*ES+ig4];
        }
        #pragma unroll
        for(int c=0;c<CH;c++) if(base+c<cnt){
            acc = fmaf(sxs[c][t]*sY[c][l], srw[c][f], acc);
            if(l==0) acc = fmaf(saw[c][f], sxs[c][f], acc);
        }
    }
    __syncthreads();
    sred[t]=acc;
    __syncthreads();
    size_t base0=(size_t)bn*LF;
    float p=0.f, sig=0.f, x0v=0.f;
    if(t<NF){
        float ss=0.f;
        #pragma unroll
        for(int l2=0;l2<NL;l2++) ss+=sred[l2*NF+t];
        x0v=d_x2[base0+t];
        sh0[t]=x0v+ss;
    }
    __syncthreads();
    if(t<NF){
        p=b1s[t];
        for(int g=0;g<NF;g++) p=fmaf(sh0[g],W1s[g*NF+t],p);
        sig=1.f/(1.f+expf(-p));
        sq[t]=p*sig;
    }
    __syncthreads();
    if(t<NF){
        float hh=0.f;
        for(int g=0;g<NF;g++) hh=fmaf(sq[g],W2s[g*NF+t],hh);
        sred[t]=(x0v+hh)*w_out[t];
        float dq=0.f;
        for(int g=0;g<NF;g++) dq=fmaf(w_out[g],W2s[t*NF+g],dq);
        sdp[t]=dq*sig*(1.f+p*(1.f-sig));
    }
    __syncthreads();
    if(t<NF){
        float dh0=0.f;
        for(int g=0;g<NF;g++) dh0=fmaf(sdp[g],W1s[t*NF+g],dh0);
        d_dh0[bn*NF+t]=dh0;
        sdh[t]=dh0;
    }
    if(t==0){
        float e=0.f;
        #pragma unroll
        for(int i=0;i<NF;i++) e+=sred[i];
        d_ae[bn]=e+ebias[z[b*NA+n]];
    }
    __syncthreads();
    d_gxA[base0+t] = (l==0)? (w_out[f]+sdh[f]) : 0.f;
}

__global__ void k_energy(float* __restrict__ out){
    int b=blockIdx.x;
    __shared__ float sh[NA];
    sh[threadIdx.x]=d_ae[b*NA+threadIdx.x];
    __syncthreads();
    for(int s=64;s>0;s>>=1){ if(threadIdx.x<s) sh[threadIdx.x]+=sh[threadIdx.x+s]; __syncthreads(); }
    if(threadIdx.x==0) out[b]=sh[0];
}

// ---------------- backward final edge (balanced phase A, writes gYR '=') ----------------
__global__ void __launch_bounds__(LF,2) kb_final_edge(const float* __restrict__ WA2, const float* __restrict__ WB2){
    int bn=blockIdx.x; int b=bn/NA;
    int t=threadIdx.x, l=t/NF, f=t%NF;
    const float* awl=d_aw[2]; const float* rwl=d_rw[2];
    __shared__ float sWA[NK*WS], sWB[NK*WS];
    __shared__ float sxj[NL*XS];
    __shared__ float sY[CH][16];
    __shared__ float saw[CH][NF], srw[CH][NF];
    __shared__ float sdm[CH][NF];
    __shared__ float sxsY[CH][NF];
    for(int i=t;i<NK*NF;i+=LF){ int k=i>>6, ff=i&63; sWA[k*WS+ff]=WA2[i]; sWB[k*WS+ff]=WB2[i]; }
    sxj[l*XS+f]=d_x2[(size_t)bn*LF+t];
    int rc=d_rcnt[bn];
    int cg6=t>>6, fg6=t&63, cg4=t>>4, ig4=t&15;
    float acc=0.f;
    float pf_dm=0.f, pf_aw=0.f, pf_rw=0.f, pf_Y=0.f;
    {
        if(t<CH*NF && cg6<rc){
            int idst=__ldg(&d_rnbr[bn*NA+cg6]);
            pf_dm=d_dh0[(b*NA+idst)*NF+fg6];
            int e=__ldg(&d_redg[bn*NA+cg6]);
            pf_aw=__ldg(&awl[(size_t)e*NF+fg6]);
            pf_rw=__ldg(&rwl[(size_t)e*NF+fg6]);
        }
        if(t<CH*16 && ig4<9 && cg4<rc){
            int e=__ldg(&d_redg[bn*NA+cg4]);
            pf_Y=d_YR[(size_t)e*ES+ig4];
        }
    }
    for(int base=0;base<rc;base+=CH){
        __syncthreads();
        if(t<CH*NF){ sdm[cg6][fg6]=pf_dm; saw[cg6][fg6]=pf_aw; srw[cg6][fg6]=pf_rw; }
        if(t<CH*16 && ig4<9) sY[cg4][ig4]=pf_Y;
        __syncthreads();
        int B=base+CH;
        if(B<rc){
            if(t<CH*NF && B+cg6<rc){
                int idst=__ldg(&d_rnbr[bn*NA+B+cg6]);
                pf_dm=d_dh0[(b*NA+idst)*NF+fg6];
                int e=__ldg(&d_redg[bn*NA+B+cg6]);
                pf_aw=__ldg(&awl[(size_t)e*NF+fg6]);
                pf_rw=__ldg(&rwl[(size_t)e*NF+fg6]);
            }
            if(t<CH*16 && ig4<9 && B+cg4<rc){
                int e=__ldg(&d_redg[bn*NA+B+cg4]);
                pf_Y=d_YR[(size_t)e*ES+ig4];
            }
        }
        // phase A: balanced xsY (512 threads, one (c,f) each)
        if(t<CH*NF){
            int c=cg6, ff=fg6;
            if(base+c<rc){
                float xsY=0.f;
                #pragma unroll
                for(int l2=0;l2<NL;l2++) xsY=fmaf(sxj[l2*XS+ff],sY[c][l2],xsY);
                sxsY[c][ff]=xsY;
            }
        }
        __syncthreads();
        // acc (all threads)
        #pragma unroll
        for(int c=0;c<CH;c++) if(base+c<rc){
            float dm=sdm[c][f], rwv=srw[c][f], Yl=sY[c][l];
            acc = fmaf(dm*Yl, rwv, acc);
            if(l==0) acc = fmaf(dm, saw[c][f], acc);
        }
        // gY: 64 groups of 8 lanes
        if(t<512){
            int g=t>>3, j=t&7, c=g>>3, l2=1+(g&7);
            if(base+c<rc){
                int fb=j*8;
                float s=0.f;
                #pragma unroll
                for(int i=0;i<8;i++)
                    s=fmaf(sdm[c][fb+i]*srw[c][fb+i], sxj[l2*XS+fb+i], s);
                s+=__shfl_down_sync(0xffffffffu,s,4,8);
                s+=__shfl_down_sync(0xffffffffu,s,2,8);
                s+=__shfl_down_sync(0xffffffffu,s,1,8);
                if(j==0){ int e=__ldg(&d_redg[bn*NA+base+c]); d_gYR[(size_t)e*ES+l2]=s; }
            }
        }
        // gR (uses sxsY from phase A)
        if(t<512){
            int c=t>>6, rem=t&63, k=rem>>2, j=rem&3, fb=j*16;
            if(base+c<rc){
                float s=0.f;
                #pragma unroll
                for(int i=0;i<16;i++){
                    float dmv=sdm[c][fb+i];
                    s=fmaf(dmv*sxj[fb+i],sWA[k*WS+fb+i],fmaf(dmv*sxsY[c][fb+i],sWB[k*WS+fb+i],s));
                }
                s+=__shfl_down_sync(0xffffffffu,s,2,4);
                s+=__shfl_down_sync(0xffffffffu,s,1,4);
                if(j==0){ int e=__ldg(&d_redg[bn*NA+base+c]); d_gYR[(size_t)e*ES+16+k]=s; }
            }
        }
    }
    d_gxA[(size_t)bn*LF+t]+=acc;
}

// ---------------- backward node ----------------
__global__ void __launch_bounds__(LF,2) kb_node(const float* __restrict__ W1, const float* __restrict__ W2, int layer){
    int bn=blockIdx.x;
    int t=threadIdx.x, l=t/NF, f=t%NF;
    int deg=c_deg[l];
    const float* gxin=(layer==1)? d_gxA : d_gxB;
    const float* y2  =(layer==1)? d_y2b : d_y2a;
    __shared__ float sgxo[LF], sy2[LF], sgy3[LF], sgy2[LF];
    size_t base=(size_t)bn*LF;
    sgxo[t]=gxin[base+t]; sy2[t]=y2[base+t];
    __syncthreads();
    const float* w2=W2+deg*4096+f*NF;
    float gy3=0.f;
    for(int g=0;g<NF;g++) gy3=fmaf(sgxo[l*NF+g],w2[g],gy3);
    sgy3[t]=gy3;
    __syncthreads();
    float s=sy2[f];
    float sig=1.f/(1.f+expf(-s));
    float gy2;
    if(l==0){
        float a=0.f;
        #pragma unroll
        for(int l2=1;l2<NL;l2++) a=fmaf(sgy3[l2*NF+f],sy2[l2*NF+f],a);
        gy2=gy3*sig*(1.f+s*(1.f-sig))+a*sig*(1.f-sig);
    } else gy2=gy3*sig;
    sgy2[t]=gy2;
    __syncthreads();
    const float* w1=W1+deg*4096+f*NF;
    float gy1=0.f;
    for(int g=0;g<NF;g++) gy1=fmaf(sgy2[l*NF+g],w1[g],gy1);
    d_gy1[base+t]=gy1;
    if(layer==1) d_gxB[base+t]=sgxo[t]+gy1;
}

// ---------------- backward layer edge (balanced phase A, gYR '+=') ----------------
__global__ void __launch_bounds__(LF,2) kb_edge(const float* __restrict__ WA, const float* __restrict__ WB, int layer){
    int bn=blockIdx.x; int b=bn/NA;
    int t=threadIdx.x, l=t/NF, f=t%NF;
    const float* xin = layer? d_x1 : d_x0;
    const float* awl=d_aw[layer]; const float* rwl=d_rw[layer];
    __shared__ float sWA[NK*WS], sWB[NK*WS];
    __shared__ float sxj[NL*XS];
    __shared__ float sY[CH][16];
    __shared__ float saw[CH][NF], srw[CH][NF];
    __shared__ float sgm[CH][NL*XS];
    __shared__ float sgmY[CH][NF], sg0[CH][NF];
    for(int i=t;i<NK*NF;i+=LF){ int k=i>>6, ff=i&63; sWA[k*WS+ff]=WA[i]; sWB[k*WS+ff]=WB[i]; }
    sxj[l*XS+f]=xin[(size_t)bn*LF+t];
    int rc=d_rcnt[bn];
    int cg6=t>>6, fg6=t&63, cg4=t>>4, ig4=t&15;
    float acc=0.f;
    float pf_gm[CH]; float pf_aw=0.f, pf_rw=0.f, pf_Y=0.f;
    {
        #pragma unroll
        for(int c=0;c<CH;c++)
            pf_gm[c] = (c<rc)? d_gy1[((size_t)b*NA+__ldg(&d_rnbr[bn*NA+c]))*LF+t] : 0.f;
        if(t<CH*NF && cg6<rc){
            int e=__ldg(&d_redg[bn*NA+cg6]);
            pf_aw=__ldg(&awl[(size_t)e*NF+fg6]);
            pf_rw=__ldg(&rwl[(size_t)e*NF+fg6]);
        }
        if(t<CH*16 && ig4<9 && cg4<rc){
            int e=__ldg(&d_redg[bn*NA+cg4]);
            pf_Y=d_YR[(size_t)e*ES+ig4];
        }
    }
    for(int base=0;base<rc;base+=CH){
        __syncthreads();
        #pragma unroll
        for(int c=0;c<CH;c++) sgm[c][l*XS+f]=pf_gm[c];
        if(t<CH*NF){ saw[cg6][fg6]=pf_aw; srw[cg6][fg6]=pf_rw; }
        if(t<CH*16 && ig4<9) sY[cg4][ig4]=pf_Y;
        __syncthreads();
        int B=base+CH;
        if(B<rc){
            #pragma unroll
            for(int c=0;c<CH;c++)
                pf_gm[c] = (B+c<rc)? d_gy1[((size_t)b*NA+__ldg(&d_rnbr[bn*NA+B+c]))*LF+t] : 0.f;
            if(t<CH*NF && B+cg6<rc){
                int e=__ldg(&d_redg[bn*NA+B+cg6]);
                pf_aw=__ldg(&awl[(size_t)e*NF+fg6]);
                pf_rw=__ldg(&rwl[(size_t)e*NF+fg6]);
            }
            if(t<CH*16 && ig4<9 && B+cg4<rc){
                int e=__ldg(&d_redg[bn*NA+B+cg4]);
                pf_Y=d_YR[(size_t)e*ES+ig4];
            }
        }
        // phase A: balanced gmY/gs0 (512 threads, one (c,f) each)
        if(t<CH*NF){
            int c=cg6, ff=fg6;
            if(base+c<rc){
                float gmY=0.f, gs0=0.f;
                #pragma unroll
                for(int l2=0;l2<NL;l2++){
                    float g2=sgm[c][l2*XS+ff];
                    gmY=fmaf(sY[c][l2],g2,gmY);
                    gs0=fmaf(g2,sxj[l2*XS+ff],gs0);
                }
                sgmY[c][ff]=gmY; sg0[c][ff]=gs0;
            }
        }
        __syncthreads();
        // acc (all threads)
        if(layer){
            #pragma unroll
            for(int c=0;c<CH;c++) if(base+c<rc){
                acc = fmaf(sgm[c][l*XS+f], srw[c][f], acc);
                if(l==0) acc = fmaf(sgmY[c][f], saw[c][f], acc);
            }
        }
        // gY
        if(t<512){
            int g=t>>3, j=t&7, c=g>>3, l2=1+(g&7);
            if(base+c<rc){
                int fb=j*8;
                float s=0.f;
                #pragma unroll
                for(int i=0;i<8;i++)
                    s=fmaf(sgm[c][l2*XS+fb+i]*saw[c][fb+i], sxj[fb+i], s);
                s+=__shfl_down_sync(0xffffffffu,s,4,8);
                s+=__shfl_down_sync(0xffffffffu,s,2,8);
                s+=__shfl_down_sync(0xffffffffu,s,1,8);
                if(j==0){ int e=__ldg(&d_redg[bn*NA+base+c]); d_gYR[(size_t)e*ES+l2]+=s; }
            }
        }
        // gR (uses sgmY/sg0 from phase A)
        if(t<512){
            int c=t>>6, rem=t&63, k=rem>>2, j=rem&3, fb=j*16;
            if(base+c<rc){
                float s=0.f;
                #pragma unroll
                for(int i=0;i<16;i++)
                    s=fmaf(sgmY[c][fb+i]*sxj[fb+i],sWA[k*WS+fb+i],fmaf(sg0[c][fb+i],sWB[k*WS+fb+i],s));
                s+=__shfl_down_sync(0xffffffffu,s,2,4);
                s+=__shfl_down_sync(0xffffffffu,s,1,4);
                if(j==0){ int e=__ldg(&d_redg[bn*NA+base+c]); d_gYR[(size_t)e*ES+16+k]+=s; }
            }
        }
    }
    if(layer==1) d_gxB[(size_t)bn*LF+t]+=acc;
}

// ---------------- basis geometry backward ----------------
__global__ void k_ddisp(const float* __restrict__ pos){
    int bn=blockIdx.x; int b=bn/NA, dst=bn%NA;
    int s=threadIdx.x;
    if(s>=d_cnt[bn]) return;
    int src=d_nbr[bn*NA+s];
    const float* pd=pos+(b*NA+dst)*3;
    const float* ps=pos+(b*NA+src)*3;
    float dx=ps[0]-pd[0], dy=ps[1]-pd[1], dz=ps[2]-pd[2];
    float r2=dx*dx+dy*dy+dz*dz+1e-12f;
    float r=sqrtf(r2), inv_r=1.f/r;
    float ux=dx*inv_r, uy=dy*inv_r, uz=dz*inv_r;
    float om=1.f-r2/CUT2;
    float cut=expf(1.f-1.f/om);
    float dcut=cut*(-2.f*r/CUT2)/(om*om);
    float w=1.f/(1.f+r), v=1.f-w, dwdr=-w*w;
    float wp[16], vp[16];
    wp[0]=1.f; vp[0]=1.f;
    #pragma unroll
    for(int q=1;q<16;q++){ wp[q]=wp[q-1]*w; vp[q]=vp[q-1]*v; }
    const float* gyr = d_gYR + ((size_t)bn*ND+s)*ES;
    float gr=0.f;
    #pragma unroll
    for(int k=0;k<16;k++){
        float rad=c_binom[k]*wp[k]*vp[15-k];
        float t1=(k>0)  ? k*wp[k-1]*vp[15-k]    : 0.f;
        float t2=(k<15) ? (15-k)*wp[k]*vp[14-k] : 0.f;
        float drd=c_binom[k]*(t1-t2)*dwdr;
        gr = fmaf(gyr[16+k], drd*cut + rad*dcut, gr);
    }
    float gY1=gyr[1],gY2=gyr[2],gY3=gyr[3],gY4=gyr[4],gY5=gyr[5],gY6=gyr[6],gY7=gyr[7],gY8=gyr[8];
    float gux=gY1+SQ3f*(gY4*uy+gY7*uz+gY8*ux);
    float guy=gY2+SQ3f*(gY4*ux+gY5*uz-gY8*uy);
    float guz=gY3+SQ3f*(gY5*uy+gY7*ux)+3.f*gY6*uz;
    float gd=gux*ux+guy*uy+guz*uz;
    float* dd=d_dd+((size_t)bn*ND+s)*3;
    dd[0]=(gux-gd*ux)*inv_r+gr*ux;
    dd[1]=(guy-gd*uy)*inv_r+gr*uy;
    dd[2]=(guz-gd*uz)*inv_r+gr*uz;
}

// ---------------- forces ----------------
__global__ void k_force(float* __restrict__ out){
    int bn=blockIdx.x;
    int s=threadIdx.x;
    float fx=0.f,fy=0.f,fz=0.f;
    int cnt=d_cnt[bn], rc=d_rcnt[bn];
    if(s<cnt){
        const float* dd=d_dd+((size_t)bn*ND+s)*3;
        fx+=dd[0]; fy+=dd[1]; fz+=dd[2];
    }
    if(s<rc){
        int e=d_redg[bn*NA+s];
        const float* dd=d_dd+(size_t)e*3;
        fx-=dd[0]; fy-=dd[1]; fz-=dd[2];
    }
    __shared__ float rx[128],ry[128],rz[128];
    rx[s]=fx; ry[s]=fy; rz[s]=fz;
    __syncthreads();
    for(int st=64;st>0;st>>=1){
        if(s<st){ rx[s]+=rx[s+st]; ry[s]+=ry[s+st]; rz[s]+=rz[s+st]; }
        __syncthreads();
    }
    if(s==0){
        float* F=out+NB+(size_t)bn*3;
        F[0]=rx[0]; F[1]=ry[0]; F[2]=rz[0];
    }
}

// ---------------- launch ----------------
extern "C" void kernel_launch(void* const* d_in, const int* in_sizes, int n_in,
                              void* d_out, int out_size){
    const int*   z     = (const int*)  d_in[0];
    const float* pos   = (const float*)d_in[1];
    const float* embed = (const float*)d_in[2];
    const float* WA    = (const float*)d_in[3];
    const float* WB    = (const float*)d_in[4];
    const float* W1    = (const float*)d_in[5];
    const float* b1    = (const float*)d_in[6];
    const float* W2    = (const float*)d_in[7];
    const float* W1s   = (const float*)d_in[8];
    const float* b1s   = (const float*)d_in[9];
    const float* W2s   = (const float*)d_in[10];
    const float* w_out = (const float*)d_in[11];
    const float* ebias = (const float*)d_in[12];
    float* out = (float*)d_out;

    k_geom<<<NB*NA,128>>>(pos);
    k_rev <<<NB*NA,128>>>();
    k_awrw<<<dim3(NB*NA,3),512>>>(WA, WB);

    // DIAGNOSTIC dummy launch: measures T(kb_final_edge) via dur delta and
    // sits in ncu's early capture window. Reads stale-but-deterministic
    // buffers; everything it writes (d_gYR '='-slots, d_gxA via +=) is fully
    // overwritten later by k_final ('=') and the real kb_final_edge ('='),
    // so final outputs are unchanged.
    kb_final_edge<<<NB*NA,LF>>>(WA+2*NK*NF, WB+2*NK*NF);

    k_init<<<NB*NA,NF>>>(z, embed);

    k_layer<<<NB*NA,LF>>>(W1+0*3*4096, b1+0*NF, W2+0*3*4096, 0);
    k_layer<<<NB*NA,LF>>>(W1+1*3*4096, b1+1*NF, W2+1*3*4096, 1);

    k_final <<<NB*NA,LF>>>(z, W1s, b1s, W2s, w_out, ebias);
    k_energy<<<NB,NA>>>(out);

    kb_final_edge<<<NB*NA,LF>>>(WA+2*NK*NF, WB+2*NK*NF);

    kb_node<<<NB*NA,LF>>>(W1+1*3*4096, W2+1*3*4096, 1);
    kb_edge<<<NB*NA,LF>>>(WA+1*NK*NF, WB+1*NK*NF, 1);
    kb_node<<<NB*NA,LF>>>(W1+0*3*4096, W2+0*3*4096, 0);
    kb_edge<<<NB*NA,LF>>>(WA+0*NK*NF, WB+0*NK*NF, 0);

    k_ddisp<<<NB*NA,128>>>(pos);
    k_force<<<NB*NA,128>>>(out);
}

// round 17
// speedup vs baseline: 1.0683x; 1.0683x over previous
#include <cuda_runtime.h>
#include <math.h>

#define NB 8
#define NA 128
#define ND 127
#define NL 9
#define NF 64
#define NK 16
#define LF (NL*NF)       // 576
#define ES 32            // per-edge stride in d_YR/d_gYR: [0..8]=Y, [16..31]=R
#define WS 65            // padded weight row stride
#define XS 65            // padded x/gm row stride
#define SQ3f 1.7320508075688772f
#define CUT2 25.0f
#define CH 8             // edge chunk

// ---------------- scratch ----------------
__device__ float d_YR [(size_t)NB*NA*ND*ES];
__device__ float d_gYR[(size_t)NB*NA*ND*ES];
__device__ float d_aw[3][(size_t)NB*NA*ND*NF];
__device__ float d_rw[3][(size_t)NB*NA*ND*NF];
__device__ float d_dd[(size_t)NB*NA*ND*3];
__device__ int   d_cnt [NB*NA];
__device__ int   d_rcnt[NB*NA];
__device__ int   d_nbr [NB*NA*NA];
__device__ int   d_slot[NB*NA*NA];
__device__ int   d_rnbr[NB*NA*NA];
__device__ int   d_redg[NB*NA*NA];
__device__ float d_x0[(size_t)NB*NA*LF];
__device__ float d_x1[(size_t)NB*NA*LF];
__device__ float d_x2[(size_t)NB*NA*LF];
__device__ float d_y2a[(size_t)NB*NA*LF];
__device__ float d_y2b[(size_t)NB*NA*LF];
__device__ float d_dh0[NB*NA*NF];
__device__ float d_gxA[(size_t)NB*NA*LF];
__device__ float d_gxB[(size_t)NB*NA*LF];
__device__ float d_gy1[(size_t)NB*NA*LF];
__device__ float d_ae[NB*NA];

__constant__ int   c_deg[9]    = {0,1,1,1,2,2,2,2,2};
__constant__ float c_binom[16] = {1.f,15.f,105.f,455.f,1365.f,3003.f,5005.f,6435.f,
                                  6435.f,5005.f,3003.f,1365.f,455.f,105.f,15.f,1.f};

// ---------------- geometry + compaction + separable basis ----------------
__global__ void k_geom(const float* __restrict__ pos){
    int bn = blockIdx.x; int b=bn/NA, dst=bn%NA;
    int j = threadIdx.x;
    float pdx=pos[(b*NA+dst)*3+0], pdy=pos[(b*NA+dst)*3+1], pdz=pos[(b*NA+dst)*3+2];
    float dx=0.f,dy=0.f,dz=0.f,r2=1.f; bool act=false;
    if(j!=dst){
        dx=pos[(b*NA+j)*3+0]-pdx;
        dy=pos[(b*NA+j)*3+1]-pdy;
        dz=pos[(b*NA+j)*3+2]-pdz;
        r2=dx*dx+dy*dy+dz*dz+1e-12f;
        act = (1.f - r2/CUT2) > 1e-6f;
    }
    unsigned m=__ballot_sync(0xffffffffu, act);
    int wid=j>>5, lane=j&31;
    __shared__ int wcnt[4];
    if(lane==0) wcnt[wid]=__popc(m);
    __syncthreads();
    int basec=0;
    #pragma unroll
    for(int w=0;w<4;w++) if(w<wid) basec+=wcnt[w];
    int slot = basec + __popc(m & ((1u<<lane)-1u));
    if(j==0) d_cnt[bn]=wcnt[0]+wcnt[1]+wcnt[2]+wcnt[3];
    d_slot[bn*NA+j] = act ? slot : -1;
    if(!act) return;
    d_nbr[bn*NA+slot]=j;
    float om = 1.f - r2/CUT2;
    float r=sqrtf(r2), inv=1.f/r;
    float ux=dx*inv, uy=dy*inv, uz=dz*inv;
    float Y[9];
    Y[0]=1.f; Y[1]=ux; Y[2]=uy; Y[3]=uz;
    Y[4]=SQ3f*ux*uy; Y[5]=SQ3f*uy*uz; Y[6]=0.5f*(3.f*uz*uz-1.f);
    Y[7]=SQ3f*ux*uz; Y[8]=0.5f*SQ3f*(ux*ux-uy*uy);
    float w=1.f/(1.f+r), v=1.f-w;
    float cut=expf(1.f-1.f/om);
    float vp[16]; vp[0]=1.f;
    #pragma unroll
    for(int q=1;q<16;q++) vp[q]=vp[q-1]*v;
    float* o = d_YR + ((size_t)bn*ND+slot)*ES;
    #pragma unroll
    for(int l=0;l<9;l++) o[l]=Y[l];
    float wk=1.f;
    #pragma unroll
    for(int k=0;k<16;k++){ o[16+k]=c_binom[k]*wk*vp[15-k]*cut; wk*=w; }
}

__global__ void k_rev(){
    int bn=blockIdx.x; int b=bn/NA, j=bn%NA;
    int i=threadIdx.x;
    int s = (i!=j) ? d_slot[(b*NA+i)*NA + j] : -1;
    bool act = s>=0;
    unsigned m=__ballot_sync(0xffffffffu, act);
    int wid=i>>5, lane=i&31;
    __shared__ int wcnt[4];
    if(lane==0) wcnt[wid]=__popc(m);
    __syncthreads();
    int basec=0;
    #pragma unroll
    for(int w=0;w<4;w++) if(w<wid) basec+=wcnt[w];
    int rslot = basec + __popc(m & ((1u<<lane)-1u));
    if(i==0) d_rcnt[bn]=wcnt[0]+wcnt[1]+wcnt[2]+wcnt[3];
    if(act){
        d_rnbr[bn*NA+rslot]=i;
        d_redg[bn*NA+rslot]=(b*NA+i)*ND + s;
    }
}

// ---------------- precompute aw/rw per edge per layer ----------------
__global__ void __launch_bounds__(512,4) k_awrw(const float* __restrict__ WA, const float* __restrict__ WB){
    int bn=blockIdx.x, lay=blockIdx.y;
    int t=threadIdx.x, c=t>>6, ff=t&63;
    __shared__ float sWA[NK*NF], sWB[NK*NF];
    const float* WAl=WA+lay*NK*NF;
    const float* WBl=WB+lay*NK*NF;
    for(int i=t;i<NK*NF;i+=512){ sWA[i]=WAl[i]; sWB[i]=WBl[i]; }
    __syncthreads();
    int cnt=d_cnt[bn];
    float* awl=d_aw[lay]; float* rwl=d_rw[lay];
    for(int base=0;base<cnt;base+=8){
        int s=base+c;
        if(s<cnt){
            const float* gR=d_YR+((size_t)bn*ND+s)*ES+16;
            float sa=0.f, sb=0.f;
            #pragma unroll
            for(int k=0;k<NK;k++){
                float rk=__ldg(&gR[k]);
                sa=fmaf(rk,sWA[k*NF+ff],sa);
                sb=fmaf(rk,sWB[k*NF+ff],sb);
            }
            size_t eo=((size_t)bn*ND+s)*NF+ff;
            awl[eo]=sa; rwl[eo]=sb;
        }
    }
}

// ---------------- init ----------------
__global__ void k_init(const int* __restrict__ z, const float* __restrict__ embed){
    int bn=blockIdx.x; int b=bn/NA, n=bn%NA;
    int f=threadIdx.x;
    float* x=d_x0+(size_t)bn*LF;
    x[f]=embed[z[b*NA+n]*NF+f];
    #pragma unroll
    for(int l=1;l<9;l++) x[l*NF+f]=0.f;
}

// ---------------- fused layer: message + node update (register-prefetch pipeline) ----------------
__global__ void __launch_bounds__(LF,2) k_layer(const float* __restrict__ W1, const float* __restrict__ b1,
                        const float* __restrict__ W2, int layer){
    int bn=blockIdx.x; int b=bn/NA;
    int t=threadIdx.x, l=t/NF, f=t%NF;
    const float* xin = layer? d_x1 : d_x0;
    float* xout = layer? d_x2 : d_x1;
    float* y2out= layer? d_y2b : d_y2a;
    const float* awl=d_aw[layer]; const float* rwl=d_rw[layer];
    __shared__ float sY[CH][16];
    __shared__ float saw[CH][NF], srw[CH][NF];
    __shared__ float sxs[CH][LF];
    __shared__ float sy[LF];
    int cnt=d_cnt[bn];
    int cg6=t>>6, fg6=t&63, cg4=t>>4, ig4=t&15;
    float xv = xin[(size_t)bn*LF+t];
    float acc = xv;
    float pf_xs[CH]; float pf_aw=0.f, pf_rw=0.f, pf_Y=0.f;
    {
        if(layer){
            #pragma unroll
            for(int c=0;c<CH;c++)
                pf_xs[c] = (c<cnt)? xin[((size_t)b*NA+__ldg(&d_nbr[bn*NA+c]))*LF+t] : 0.f;
        } else {
            if(t<CH*NF)
                pf_xs[0] = (cg6<cnt)? xin[((size_t)b*NA+__ldg(&d_nbr[bn*NA+cg6]))*LF+fg6] : 0.f;
        }
        if(t<CH*NF && cg6<cnt){
            size_t eo=((size_t)bn*ND+cg6)*NF+fg6;
            pf_aw=__ldg(&awl[eo]); pf_rw=__ldg(&rwl[eo]);
        }
        if(t<CH*16 && ig4<9 && cg4<cnt)
            pf_Y=d_YR[((size_t)bn*ND+cg4)*ES+ig4];
    }
    for(int base=0;base<cnt;base+=CH){
        __syncthreads();
        if(layer){
            #pragma unroll
            for(int c=0;c<CH;c++) sxs[c][t]=pf_xs[c];
        } else {
            if(t<CH*NF) sxs[cg6][fg6]=pf_xs[0];
        }
        if(t<CH*NF){ saw[cg6][fg6]=pf_aw; srw[cg6][fg6]=pf_rw; }
        if(t<CH*16 && ig4<9) sY[cg4][ig4]=pf_Y;
        __syncthreads();
        int B=base+CH;
        if(B<cnt){
            if(layer){
                #pragma unroll
                for(int c=0;c<CH;c++)
                    pf_xs[c] = (B+c<cnt)? xin[((size_t)b*NA+__ldg(&d_nbr[bn*NA+B+c]))*LF+t] : 0.f;
            } else {
                if(t<CH*NF)
                    pf_xs[0] = (B+cg6<cnt)? xin[((size_t)b*NA+__ldg(&d_nbr[bn*NA+B+cg6]))*LF+fg6] : 0.f;
            }
            if(t<CH*NF && B+cg6<cnt){
                size_t eo=((size_t)bn*ND+B+cg6)*NF+fg6;
                pf_aw=__ldg(&awl[eo]); pf_rw=__ldg(&rwl[eo]);
            }
            if(t<CH*16 && ig4<9 && B+cg4<cnt)
                pf_Y=d_YR[((size_t)bn*ND+B+cg4)*ES+ig4];
        }
        #pragma unroll
        for(int c=0;c<CH;c++) if(base+c<cnt){
            float xs0=sxs[c][f];
            acc = fmaf(sY[c][l]*saw[c][f], xs0, acc);
            if(layer) acc = fmaf(sxs[c][t], srw[c][f], acc);
            else if(l==0) acc = fmaf(xs0, srw[c][f], acc);
        }
    }
    // node phase
    __syncthreads();
    sy[t]=acc;
    __syncthreads();
    int deg=c_deg[l];
    const float* w1=W1+deg*4096;
    float v=0.f;
    for(int h=0;h<NF;h++) v=fmaf(sy[l*NF+h],w1[h*NF+f],v);
    if(l==0) v+=b1[f];
    y2out[(size_t)bn*LF+t]=v;
    __syncthreads();
    sy[t]=v;
    __syncthreads();
    float s=sy[f];
    float sig=1.f/(1.f+expf(-s));
    float y3=(l==0)? s*sig : v*sig;
    __syncthreads();
    sy[t]=y3;
    __syncthreads();
    const float* w2=W2+deg*4096;
    float o=0.f;
    for(int h=0;h<NF;h++) o=fmaf(sy[l*NF+h],w2[h*NF+f],o);
    xout[(size_t)bn*LF+t]=xv+o;
}

// ---------------- fused final: edge messages + scalar MLP fwd/bwd (pipelined) ----------------
__global__ void __launch_bounds__(LF,2) k_final(const int* __restrict__ z,
                        const float* __restrict__ W1s, const float* __restrict__ b1s,
                        const float* __restrict__ W2s, const float* __restrict__ w_out,
                        const float* __restrict__ ebias){
    int bn=blockIdx.x; int b=bn/NA, n=bn%NA;
    int t=threadIdx.x, l=t/NF, f=t%NF;
    const float* awl=d_aw[2]; const float* rwl=d_rw[2];
    __shared__ float sY[CH][16];
    __shared__ float saw[CH][NF], srw[CH][NF];
    __shared__ float sxs[CH][LF];
    __shared__ float sred[LF];
    __shared__ float sh0[NF], sq[NF], sdp[NF], sdh[NF];
    int cnt=d_cnt[bn];
    int cg6=t>>6, fg6=t&63, cg4=t>>4, ig4=t&15;
    float acc=0.f;
    float pf_xs[CH]; float pf_aw=0.f, pf_rw=0.f, pf_Y=0.f;
    {
        #pragma unroll
        for(int c=0;c<CH;c++)
            pf_xs[c] = (c<cnt)? d_x2[((size_t)b*NA+__ldg(&d_nbr[bn*NA+c]))*LF+t] : 0.f;
        if(t<CH*NF && cg6<cnt){
            size_t eo=((size_t)bn*ND+cg6)*NF+fg6;
            pf_aw=__ldg(&awl[eo]); pf_rw=__ldg(&rwl[eo]);
        }
        if(t<CH*16 && ig4<9 && cg4<cnt)
            pf_Y=d_YR[((size_t)bn*ND+cg4)*ES+ig4];
    }
    for(int base=0;base<cnt;base+=CH){
        __syncthreads();
        #pragma unroll
        for(int c=0;c<CH;c++) sxs[c][t]=pf_xs[c];
        if(t<CH*NF){ saw[cg6][fg6]=pf_aw; srw[cg6][fg6]=pf_rw; }
        if(t<CH*16 && ig4<9) sY[cg4][ig4]=pf_Y;
        __syncthreads();
        int B=base+CH;
        if(B<cnt){
            #pragma unroll
            for(int c=0;c<CH;c++)
                pf_xs[c] = (B+c<cnt)? d_x2[((size_t)b*NA+__ldg(&d_nbr[bn*NA+B+c]))*LF+t] : 0.f;
            if(t<CH*NF && B+cg6<cnt){
                size_t eo=((size_t)bn*ND+B+cg6)*NF+fg6;
                pf_aw=__ldg(&awl[eo]); pf_rw=__ldg(&rwl[eo]);
            }
            if(t<CH*16 && ig4<9 && B+cg4<cnt)
                pf_Y=d_YR[((size_t)bn*ND+B+cg4)*ES+ig4];
        }
        #pragma unroll
        for(int c=0;c<CH;c++) if(base+c<cnt){
            acc = fmaf(sxs[c][t]*sY[c][l], srw[c][f], acc);
            if(l==0) acc = fmaf(saw[c][f], sxs[c][f], acc);
        }
    }
    __syncthreads();
    sred[t]=acc;
    __syncthreads();
    size_t base0=(size_t)bn*LF;
    float p=0.f, sig=0.f, x0v=0.f;
    if(t<NF){
        float ss=0.f;
        #pragma unroll
        for(int l2=0;l2<NL;l2++) ss+=sred[l2*NF+t];
        x0v=d_x2[base0+t];
        sh0[t]=x0v+ss;
    }
    __syncthreads();
    if(t<NF){
        p=b1s[t];
        for(int g=0;g<NF;g++) p=fmaf(sh0[g],W1s[g*NF+t],p);
        sig=1.f/(1.f+expf(-p));
        sq[t]=p*sig;
    }
    __syncthreads();
    if(t<NF){
        float hh=0.f;
        for(int g=0;g<NF;g++) hh=fmaf(sq[g],W2s[g*NF+t],hh);
        sred[t]=(x0v+hh)*w_out[t];
        float dq=0.f;
        for(int g=0;g<NF;g++) dq=fmaf(w_out[g],W2s[t*NF+g],dq);
        sdp[t]=dq*sig*(1.f+p*(1.f-sig));
    }
    __syncthreads();
    if(t<NF){
        float dh0=0.f;
        for(int g=0;g<NF;g++) dh0=fmaf(sdp[g],W1s[t*NF+g],dh0);
        d_dh0[bn*NF+t]=dh0;
        sdh[t]=dh0;
    }
    if(t==0){
        float e=0.f;
        #pragma unroll
        for(int i=0;i<NF;i++) e+=sred[i];
        d_ae[bn]=e+ebias[z[b*NA+n]];
    }
    __syncthreads();
    d_gxA[base0+t] = (l==0)? (w_out[f]+sdh[f]) : 0.f;
}

__global__ void k_energy(float* __restrict__ out){
    int b=blockIdx.x;
    __shared__ float sh[NA];
    sh[threadIdx.x]=d_ae[b*NA+threadIdx.x];
    __syncthreads();
    for(int s=64;s>0;s>>=1){ if(threadIdx.x<s) sh[threadIdx.x]+=sh[threadIdx.x+s]; __syncthreads(); }
    if(threadIdx.x==0) out[b]=sh[0];
}

// ---------------- backward final edge (balanced phase A, staged redg, writes gYR '=') ----------------
__global__ void __launch_bounds__(LF,2) kb_final_edge(const float* __restrict__ WA2, const float* __restrict__ WB2){
    int bn=blockIdx.x; int b=bn/NA;
    int t=threadIdx.x, l=t/NF, f=t%NF;
    const float* awl=d_aw[2]; const float* rwl=d_rw[2];
    __shared__ float sWA[NK*WS], sWB[NK*WS];
    __shared__ float sxj[NL*XS];
    __shared__ float sY[CH][16];
    __shared__ float saw[CH][NF], srw[CH][NF];
    __shared__ float sdm[CH][NF];
    __shared__ float sxsY[CH][NF];
    __shared__ int sre[CH];
    for(int i=t;i<NK*NF;i+=LF){ int k=i>>6, ff=i&63; sWA[k*WS+ff]=WA2[i]; sWB[k*WS+ff]=WB2[i]; }
    sxj[l*XS+f]=d_x2[(size_t)bn*LF+t];
    int rc=d_rcnt[bn];
    int cg6=t>>6, fg6=t&63, cg4=t>>4, ig4=t&15;
    float acc=0.f;
    float pf_dm=0.f, pf_aw=0.f, pf_rw=0.f, pf_Y=0.f;
    {
        if(t<CH*NF && cg6<rc){
            int idst=__ldg(&d_rnbr[bn*NA+cg6]);
            pf_dm=d_dh0[(b*NA+idst)*NF+fg6];
            int e=__ldg(&d_redg[bn*NA+cg6]);
            pf_aw=__ldg(&awl[(size_t)e*NF+fg6]);
            pf_rw=__ldg(&rwl[(size_t)e*NF+fg6]);
        }
        if(t<CH*16 && ig4<9 && cg4<rc){
            int e=__ldg(&d_redg[bn*NA+cg4]);
            pf_Y=d_YR[(size_t)e*ES+ig4];
        }
    }
    for(int base=0;base<rc;base+=CH){
        __syncthreads();
        if(t<CH*NF){ sdm[cg6][fg6]=pf_dm; saw[cg6][fg6]=pf_aw; srw[cg6][fg6]=pf_rw; }
        if(t<CH*16 && ig4<9) sY[cg4][ig4]=pf_Y;
        if(t<CH && base+t<rc) sre[t]=__ldg(&d_redg[bn*NA+base+t]);
        __syncthreads();
        int B=base+CH;
        if(B<rc){
            if(t<CH*NF && B+cg6<rc){
                int idst=__ldg(&d_rnbr[bn*NA+B+cg6]);
                pf_dm=d_dh0[(b*NA+idst)*NF+fg6];
                int e=__ldg(&d_redg[bn*NA+B+cg6]);
                pf_aw=__ldg(&awl[(size_t)e*NF+fg6]);
                pf_rw=__ldg(&rwl[(size_t)e*NF+fg6]);
            }
            if(t<CH*16 && ig4<9 && B+cg4<rc){
                int e=__ldg(&d_redg[bn*NA+B+cg4]);
                pf_Y=d_YR[(size_t)e*ES+ig4];
            }
        }
        // phase A: balanced xsY (512 threads, one (c,f) each)
        if(t<CH*NF){
            int c=cg6, ff=fg6;
            if(base+c<rc){
                float xsY=0.f;
                #pragma unroll
                for(int l2=0;l2<NL;l2++) xsY=fmaf(sxj[l2*XS+ff],sY[c][l2],xsY);
                sxsY[c][ff]=xsY;
            }
        }
        __syncthreads();
        // acc (all threads)
        #pragma unroll
        for(int c=0;c<CH;c++) if(base+c<rc){
            float dm=sdm[c][f], rwv=srw[c][f], Yl=sY[c][l];
            acc = fmaf(dm*Yl, rwv, acc);
            if(l==0) acc = fmaf(dm, saw[c][f], acc);
        }
        // gY: 64 groups of 8 lanes
        if(t<512){
            int g=t>>3, j=t&7, c=g>>3, l2=1+(g&7);
            if(base+c<rc){
                int fb=j*8;
                float s=0.f;
                #pragma unroll
                for(int i=0;i<8;i++)
                    s=fmaf(sdm[c][fb+i]*srw[c][fb+i], sxj[l2*XS+fb+i], s);
                s+=__shfl_down_sync(0xffffffffu,s,4,8);
                s+=__shfl_down_sync(0xffffffffu,s,2,8);
                s+=__shfl_down_sync(0xffffffffu,s,1,8);
                if(j==0) d_gYR[(size_t)sre[c]*ES+l2]=s;
            }
        }
        // gR (uses sxsY from phase A)
        if(t<512){
            int c=t>>6, rem=t&63, k=rem>>2, j=rem&3, fb=j*16;
            if(base+c<rc){
                float s=0.f;
                #pragma unroll
                for(int i=0;i<16;i++){
                    float dmv=sdm[c][fb+i];
                    s=fmaf(dmv*sxj[fb+i],sWA[k*WS+fb+i],fmaf(dmv*sxsY[c][fb+i],sWB[k*WS+fb+i],s));
                }
                s+=__shfl_down_sync(0xffffffffu,s,2,4);
                s+=__shfl_down_sync(0xffffffffu,s,1,4);
                if(j==0) d_gYR[(size_t)sre[c]*ES+16+k]=s;
            }
        }
    }
    d_gxA[(size_t)bn*LF+t]+=acc;
}

// ---------------- backward node ----------------
__global__ void __launch_bounds__(LF,2) kb_node(const float* __restrict__ W1, const float* __restrict__ W2, int layer){
    int bn=blockIdx.x;
    int t=threadIdx.x, l=t/NF, f=t%NF;
    int deg=c_deg[l];
    const float* gxin=(layer==1)? d_gxA : d_gxB;
    const float* y2  =(layer==1)? d_y2b : d_y2a;
    __shared__ float sgxo[LF], sy2[LF], sgy3[LF], sgy2[LF];
    size_t base=(size_t)bn*LF;
    sgxo[t]=gxin[base+t]; sy2[t]=y2[base+t];
    __syncthreads();
    const float* w2=W2+deg*4096+f*NF;
    float gy3=0.f;
    for(int g=0;g<NF;g++) gy3=fmaf(sgxo[l*NF+g],w2[g],gy3);
    sgy3[t]=gy3;
    __syncthreads();
    float s=sy2[f];
    float sig=1.f/(1.f+expf(-s));
    float gy2;
    if(l==0){
        float a=0.f;
        #pragma unroll
        for(int l2=1;l2<NL;l2++) a=fmaf(sgy3[l2*NF+f],sy2[l2*NF+f],a);
        gy2=gy3*sig*(1.f+s*(1.f-sig))+a*sig*(1.f-sig);
    } else gy2=gy3*sig;
    sgy2[t]=gy2;
    __syncthreads();
    const float* w1=W1+deg*4096+f*NF;
    float gy1=0.f;
    for(int g=0;g<NF;g++) gy1=fmaf(sgy2[l*NF+g],w1[g],gy1);
    d_gy1[base+t]=gy1;
    if(layer==1) d_gxB[base+t]=sgxo[t]+gy1;
}

// ---------------- backward layer edge (balanced phase A, staged redg, gYR '+=') ----------------
__global__ void __launch_bounds__(LF,2) kb_edge(const float* __restrict__ WA, const float* __restrict__ WB, int layer){
    int bn=blockIdx.x; int b=bn/NA;
    int t=threadIdx.x, l=t/NF, f=t%NF;
    const float* xin = layer? d_x1 : d_x0;
    const float* awl=d_aw[layer]; const float* rwl=d_rw[layer];
    __shared__ float sWA[NK*WS], sWB[NK*WS];
    __shared__ float sxj[NL*XS];
    __shared__ float sY[CH][16];
    __shared__ float saw[CH][NF], srw[CH][NF];
    __shared__ float sgm[CH][NL*XS];
    __shared__ float sgmY[CH][NF], sg0[CH][NF];
    __shared__ int sre[CH];
    for(int i=t;i<NK*NF;i+=LF){ int k=i>>6, ff=i&63; sWA[k*WS+ff]=WA[i]; sWB[k*WS+ff]=WB[i]; }
    sxj[l*XS+f]=xin[(size_t)bn*LF+t];
    int rc=d_rcnt[bn];
    int cg6=t>>6, fg6=t&63, cg4=t>>4, ig4=t&15;
    float acc=0.f;
    float pf_gm[CH]; float pf_aw=0.f, pf_rw=0.f, pf_Y=0.f;
    {
        #pragma unroll
        for(int c=0;c<CH;c++)
            pf_gm[c] = (c<rc)? d_gy1[((size_t)b*NA+__ldg(&d_rnbr[bn*NA+c]))*LF+t] : 0.f;
        if(t<CH*NF && cg6<rc){
            int e=__ldg(&d_redg[bn*NA+cg6]);
            pf_aw=__ldg(&awl[(size_t)e*NF+fg6]);
            pf_rw=__ldg(&rwl[(size_t)e*NF+fg6]);
        }
        if(t<CH*16 && ig4<9 && cg4<rc){
            int e=__ldg(&d_redg[bn*NA+cg4]);
            pf_Y=d_YR[(size_t)e*ES+ig4];
        }
    }
    for(int base=0;base<rc;base+=CH){
        __syncthreads();
        #pragma unroll
        for(int c=0;c<CH;c++) sgm[c][l*XS+f]=pf_gm[c];
        if(t<CH*NF){ saw[cg6][fg6]=pf_aw; srw[cg6][fg6]=pf_rw; }
        if(t<CH*16 && ig4<9) sY[cg4][ig4]=pf_Y;
        if(t<CH && base+t<rc) sre[t]=__ldg(&d_redg[bn*NA+base+t]);
        __syncthreads();
        int B=base+CH;
        if(B<rc){
            #pragma unroll
            for(int c=0;c<CH;c++)
                pf_gm[c] = (B+c<rc)? d_gy1[((size_t)b*NA+__ldg(&d_rnbr[bn*NA+B+c]))*LF+t] : 0.f;
            if(t<CH*NF && B+cg6<rc){
                int e=__ldg(&d_redg[bn*NA+B+cg6]);
                pf_aw=__ldg(&awl[(size_t)e*NF+fg6]);
                pf_rw=__ldg(&rwl[(size_t)e*NF+fg6]);
            }
            if(t<CH*16 && ig4<9 && B+cg4<rc){
                int e=__ldg(&d_redg[bn*NA+B+cg4]);
                pf_Y=d_YR[(size_t)e*ES+ig4];
            }
        }
        // phase A: balanced gmY/gs0 (512 threads, one (c,f) each)
        if(t<CH*NF){
            int c=cg6, ff=fg6;
            if(base+c<rc){
                float gmY=0.f, gs0=0.f;
                #pragma unroll
                for(int l2=0;l2<NL;l2++){
                    float g2=sgm[c][l2*XS+ff];
                    gmY=fmaf(sY[c][l2],g2,gmY);
                    gs0=fmaf(g2,sxj[l2*XS+ff],gs0);
                }
                sgmY[c][ff]=gmY; sg0[c][ff]=gs0;
            }
        }
        __syncthreads();
        // acc (all threads)
        if(layer){
            #pragma unroll
            for(int c=0;c<CH;c++) if(base+c<rc){
                acc = fmaf(sgm[c][l*XS+f], srw[c][f], acc);
                if(l==0) acc = fmaf(sgmY[c][f], saw[c][f], acc);
            }
        }
        // gY
        if(t<512){
            int g=t>>3, j=t&7, c=g>>3, l2=1+(g&7);
            if(base+c<rc){
                int fb=j*8;
                float s=0.f;
                #pragma unroll
                for(int i=0;i<8;i++)
                    s=fmaf(sgm[c][l2*XS+fb+i]*saw[c][fb+i], sxj[fb+i], s);
                s+=__shfl_down_sync(0xffffffffu,s,4,8);
                s+=__shfl_down_sync(0xffffffffu,s,2,8);
                s+=__shfl_down_sync(0xffffffffu,s,1,8);
                if(j==0) d_gYR[(size_t)sre[c]*ES+l2]+=s;
            }
        }
        // gR (uses sgmY/sg0 from phase A)
        if(t<512){
            int c=t>>6, rem=t&63, k=rem>>2, j=rem&3, fb=j*16;
            if(base+c<rc){
                float s=0.f;
                #pragma unroll
                for(int i=0;i<16;i++)
                    s=fmaf(sgmY[c][fb+i]*sxj[fb+i],sWA[k*WS+fb+i],fmaf(sg0[c][fb+i],sWB[k*WS+fb+i],s));
                s+=__shfl_down_sync(0xffffffffu,s,2,4);
                s+=__shfl_down_sync(0xffffffffu,s,1,4);
                if(j==0) d_gYR[(size_t)sre[c]*ES+16+k]+=s;
            }
        }
    }
    if(layer==1) d_gxB[(size_t)bn*LF+t]+=acc;
}

// ---------------- basis geometry backward ----------------
__global__ void k_ddisp(const float* __restrict__ pos){
    int bn=blockIdx.x; int b=bn/NA, dst=bn%NA;
    int s=threadIdx.x;
    if(s>=d_cnt[bn]) return;
    int src=d_nbr[bn*NA+s];
    const float* pd=pos+(b*NA+dst)*3;
    const float* ps=pos+(b*NA+src)*3;
    float dx=ps[0]-pd[0], dy=ps[1]-pd[1], dz=ps[2]-pd[2];
    float r2=dx*dx+dy*dy+dz*dz+1e-12f;
    float r=sqrtf(r2), inv_r=1.f/r;
    float ux=dx*inv_r, uy=dy*inv_r, uz=dz*inv_r;
    float om=1.f-r2/CUT2;
    float cut=expf(1.f-1.f/om);
    float dcut=cut*(-2.f*r/CUT2)/(om*om);
    float w=1.f/(1.f+r), v=1.f-w, dwdr=-w*w;
    float wp[16], vp[16];
    wp[0]=1.f; vp[0]=1.f;
    #pragma unroll
    for(int q=1;q<16;q++){ wp[q]=wp[q-1]*w; vp[q]=vp[q-1]*v; }
    const float* gyr = d_gYR + ((size_t)bn*ND+s)*ES;
    float gr=0.f;
    #pragma unroll
    for(int k=0;k<16;k++){
        float rad=c_binom[k]*wp[k]*vp[15-k];
        float t1=(k>0)  ? k*wp[k-1]*vp[15-k]    : 0.f;
        float t2=(k<15) ? (15-k)*wp[k]*vp[14-k] : 0.f;
        float drd=c_binom[k]*(t1-t2)*dwdr;
        gr = fmaf(gyr[16+k], drd*cut + rad*dcut, gr);
    }
    float gY1=gyr[1],gY2=gyr[2],gY3=gyr[3],gY4=gyr[4],gY5=gyr[5],gY6=gyr[6],gY7=gyr[7],gY8=gyr[8];
    float gux=gY1+SQ3f*(gY4*uy+gY7*uz+gY8*ux);
    float guy=gY2+SQ3f*(gY4*ux+gY5*uz-gY8*uy);
    float guz=gY3+SQ3f*(gY5*uy+gY7*ux)+3.f*gY6*uz;
    float gd=gux*ux+guy*uy+guz*uz;
    float* dd=d_dd+((size_t)bn*ND+s)*3;
    dd[0]=(gux-gd*ux)*inv_r+gr*ux;
    dd[1]=(guy-gd*uy)*inv_r+gr*uy;
    dd[2]=(guz-gd*uz)*inv_r+gr*uz;
}

// ---------------- forces ----------------
__global__ void k_force(float* __restrict__ out){
    int bn=blockIdx.x;
    int s=threadIdx.x;
    float fx=0.f,fy=0.f,fz=0.f;
    int cnt=d_cnt[bn], rc=d_rcnt[bn];
    if(s<cnt){
        const float* dd=d_dd+((size_t)bn*ND+s)*3;
        fx+=dd[0]; fy+=dd[1]; fz+=dd[2];
    }
    if(s<rc){
        int e=d_redg[bn*NA+s];
        const float* dd=d_dd+(size_t)e*3;
        fx-=dd[0]; fy-=dd[1]; fz-=dd[2];
    }
    __shared__ float rx[128],ry[128],rz[128];
    rx[s]=fx; ry[s]=fy; rz[s]=fz;
    __syncthreads();
    for(int st=64;st>0;st>>=1){
        if(s<st){ rx[s]+=rx[s+st]; ry[s]+=ry[s+st]; rz[s]+=rz[s+st]; }
        __syncthreads();
    }
    if(s==0){
        float* F=out+NB+(size_t)bn*3;
        F[0]=rx[0]; F[1]=ry[0]; F[2]=rz[0];
    }
}

// ---------------- launch ----------------
extern "C" void kernel_launch(void* const* d_in, const int* in_sizes, int n_in,
                              void* d_out, int out_size){
    const int*   z     = (const int*)  d_in[0];
    const float* pos   = (const float*)d_in[1];
    const float* embed = (const float*)d_in[2];
    const float* WA    = (const float*)d_in[3];
    const float* WB    = (const float*)d_in[4];
    const float* W1    = (const float*)d_in[5];
    const float* b1    = (const float*)d_in[6];
    const float* W2    = (const float*)d_in[7];
    const float* W1s   = (const float*)d_in[8];
    const float* b1s   = (const float*)d_in[9];
    const float* W2s   = (const float*)d_in[10];
    const float* w_out = (const float*)d_in[11];
    const float* ebias = (const float*)d_in[12];
    float* out = (float*)d_out;

    k_geom<<<NB*NA,128>>>(pos);
    k_rev <<<NB*NA,128>>>();
    k_awrw<<<dim3(NB*NA,3),512>>>(WA, WB);
    k_init<<<NB*NA,NF>>>(z, embed);

    k_layer<<<NB*NA,LF>>>(W1+0*3*4096, b1+0*NF, W2+0*3*4096, 0);
    k_layer<<<NB*NA,LF>>>(W1+1*3*4096, b1+1*NF, W2+1*3*4096, 1);

    k_final <<<NB*NA,LF>>>(z, W1s, b1s, W2s, w_out, ebias);
    k_energy<<<NB,NA>>>(out);

    kb_final_edge<<<NB*NA,LF>>>(WA+2*NK*NF, WB+2*NK*NF);

    kb_node<<<NB*NA,LF>>>(W1+1*3*4096, W2+1*3*4096, 1);
    kb_edge<<<NB*NA,LF>>>(WA+1*NK*NF, WB+1*NK*NF, 1);
    kb_node<<<NB*NA,LF>>>(W1+0*3*4096, W2+0*3*4096, 0);
    kb_edge<<<NB*NA,LF>>>(WA+0*NK*NF, WB+0*NK*NF, 0);

    k_ddisp<<<NB*NA,128>>>(pos);
    k_force<<<NB*NA,128>>>(out);
}